// round 6
// baseline (speedup 1.0000x reference)
#include <cuda_runtime.h>
#include <cuda_bf16.h>
#include <mma.h>
#include <cstdint>

// Problem constants
#define BB 2
#define SS 4096
#define DD 512
#define HH 8
#define DKK 64
#define MTOT (BB * SS)   // 8192

// scale folded into Q projection: 1/sqrt(64) * log2(e)
#define QSCALE 0.18033688011112042f

// ---------------------------------------------------------------------------
// Scratch (device globals; no allocation allowed)
// ---------------------------------------------------------------------------
__device__ float g_Qh[BB * HH * SS * DKK];   // [b][h][s][dk]
__device__ float g_Kh[BB * HH * SS * DKK];
__device__ float g_Vh[BB * HH * SS * DKK];
__device__ float g_AO[BB * SS * DD];         // [b][s][h*64+dk]
__device__ int   g_kidx[BB * SS];
__device__ int   g_kcnt[BB];

// ---------------------------------------------------------------------------
// Mask compaction (stable, deterministic)
// ---------------------------------------------------------------------------
__global__ void compact_mask_kernel(const int* __restrict__ mask) {
    int b = blockIdx.x;
    const int* mb = mask + b * SS;
    int lane = threadIdx.x;  // 32 threads
    int base = 0;
    for (int c = 0; c < SS; c += 32) {
        int v = (mb[c + lane] != 0);
        unsigned bal = __ballot_sync(0xffffffffu, v);
        int pos = base + __popc(bal & ((1u << lane) - 1u));
        if (v) g_kidx[b * SS + pos] = c + lane;
        base += __popc(bal);
    }
    if (lane == 0) g_kcnt[b] = base;
}

// ---------------------------------------------------------------------------
// Helpers
// ---------------------------------------------------------------------------
__device__ __forceinline__ float f2tf(float x) {
    uint32_t u;
    asm("cvt.rna.tf32.f32 %0, %1;" : "=r"(u) : "f"(x));
    return __uint_as_float(u);
}

__device__ __forceinline__ uint32_t f2tfu(float x) {
    uint32_t u;
    asm("cvt.rna.tf32.f32 %0, %1;" : "=r"(u) : "f"(x));
    return u;
}

__device__ __forceinline__ void mma_tf32(float* c, const uint32_t* a,
                                         uint32_t b0, uint32_t b1) {
    asm volatile(
        "mma.sync.aligned.m16n8k8.row.col.f32.tf32.tf32.f32 "
        "{%0,%1,%2,%3}, {%4,%5,%6,%7}, {%8,%9}, {%0,%1,%2,%3};\n"
        : "+f"(c[0]), "+f"(c[1]), "+f"(c[2]), "+f"(c[3])
        : "r"(a[0]), "r"(a[1]), "r"(a[2]), "r"(a[3]), "r"(b0), "r"(b1));
}

__device__ __forceinline__ void ldsm_x4(uint32_t* d, uint32_t saddr) {
    asm volatile(
        "ldmatrix.sync.aligned.m8n8.x4.shared.b16 {%0,%1,%2,%3}, [%4];"
        : "=r"(d[0]), "=r"(d[1]), "=r"(d[2]), "=r"(d[3]) : "r"(saddr));
}

__device__ __forceinline__ void cp_async16(float* smem_dst, const float* gsrc) {
    unsigned sa = (unsigned)__cvta_generic_to_shared(smem_dst);
    asm volatile("cp.async.cg.shared.global [%0], [%1], 16;" :: "r"(sa), "l"(gsrc));
}

__device__ __forceinline__ uint32_t smem_u32(const void* p) {
    return (uint32_t)__cvta_generic_to_shared(p);
}

// ---------------------------------------------------------------------------
// Fused QKV GEMM: C[M,512] = X[M,512] @ W^T, mma.m16n8k8 tf32, cp.async
// double-buffered, ldmatrix fragment loads. grid.z selects (q/k/v).
// Epilogue writes head-major [b][h][s][dk]; z==0 applies QSCALE.
// ---------------------------------------------------------------------------
#define G_BM 128
#define G_BN 128
#define G_BK 32
#define G_LDA 36    // rows 144B (16B-mult); LDSM bank pattern 4r+c: conflict-free
#define G_STAGE (G_BM * G_LDA + G_BN * G_LDA)
#define G_NIT (DD / G_BK)   // 16

template <bool HEADOUT>
__global__ __launch_bounds__(256, 2) void gemm3_kernel(
    const float* __restrict__ X0, const float* __restrict__ W0,
    float* __restrict__ O0,
    const float* __restrict__ X1, const float* __restrict__ W1,
    float* __restrict__ O1,
    const float* __restrict__ X2, const float* __restrict__ W2,
    float* __restrict__ O2)
{
    extern __shared__ float smem[];

    const int z = blockIdx.z;
    const float* X = (z == 0) ? X0 : (z == 1) ? X1 : X2;
    const float* W = (z == 0) ? W0 : (z == 1) ? W1 : W2;
    float*     Out = (z == 0) ? O0 : (z == 1) ? O1 : O2;
    const bool scale = HEADOUT && (z == 0);

    const int m0 = blockIdx.x * G_BM;
    const int n0 = blockIdx.y * G_BN;
    const int tid  = threadIdx.x;
    const int lane = tid & 31;
    const int w    = tid >> 5;
    const int g    = lane >> 2;
    const int t    = lane & 3;
    const int wm   = w >> 2;   // 0..1 : 64-row strip
    const int wn   = w & 3;    // 0..3 : 32-col strip

    // ldmatrix per-lane offsets (elements)
    const int lm = lane >> 3, lr = lane & 7;
    const uint32_t offA = (uint32_t)(((lm & 1) * 8 + lr) * G_LDA + (lm >> 1) * 4);
    const uint32_t offB = (uint32_t)(((lm >> 1) * 8 + lr) * G_LDA + (lm & 1) * 4);

    float acc[4][4][4];
#pragma unroll
    for (int mt = 0; mt < 4; mt++)
#pragma unroll
        for (int nt = 0; nt < 4; nt++)
#pragma unroll
            for (int e = 0; e < 4; e++) acc[mt][nt][e] = 0.0f;

    auto load_stage = [&](int s, int k0) {
        float* As = smem + s * G_STAGE;
        float* Bs = As + G_BM * G_LDA;
#pragma unroll
        for (int j = 0; j < 4; j++) {
            int idx = tid * 4 + j;         // 0..1023
            int r = idx >> 3, seg = idx & 7;
            cp_async16(&As[r * G_LDA + seg * 4],
                       &X[(size_t)(m0 + r) * DD + k0 + seg * 4]);
            cp_async16(&Bs[r * G_LDA + seg * 4],
                       &W[(size_t)(n0 + r) * DD + k0 + seg * 4]);
        }
        asm volatile("cp.async.commit_group;" ::: "memory");
    };

    load_stage(0, 0);

    for (int it = 0; it < G_NIT; it++) {
        asm volatile("cp.async.wait_group 0;" ::: "memory");
        __syncthreads();
        if (it + 1 < G_NIT) load_stage((it + 1) & 1, (it + 1) * G_BK);

        const float* As = smem + (it & 1) * G_STAGE;
        const float* Bs = As + G_BM * G_LDA;
        const uint32_t aBase = smem_u32(As) + offA * 4;
        const uint32_t bBase = smem_u32(Bs) + offB * 4;

#pragma unroll
        for (int ks = 0; ks < 4; ks++) {
            uint32_t af[4][4];
            uint32_t bf[4][2];
#pragma unroll
            for (int mt = 0; mt < 4; mt++) {
                ldsm_x4(af[mt], aBase + (uint32_t)(((wm * 64 + mt * 16) * G_LDA + ks * 8) * 4));
#pragma unroll
                for (int e = 0; e < 4; e++)
                    af[mt][e] = f2tfu(__uint_as_float(af[mt][e]));
            }
#pragma unroll
            for (int np = 0; np < 2; np++) {
                uint32_t bb[4];
                ldsm_x4(bb, bBase + (uint32_t)(((wn * 32 + np * 16) * G_LDA + ks * 8) * 4));
#pragma unroll
                for (int e = 0; e < 4; e++)
                    bb[e] = f2tfu(__uint_as_float(bb[e]));
                bf[2 * np][0] = bb[0]; bf[2 * np][1] = bb[1];
                bf[2 * np + 1][0] = bb[2]; bf[2 * np + 1][1] = bb[3];
            }
#pragma unroll
            for (int mt = 0; mt < 4; mt++)
#pragma unroll
                for (int nt = 0; nt < 4; nt++)
                    mma_tf32(acc[mt][nt], af[mt], bf[nt][0], bf[nt][1]);
        }
        __syncthreads();
    }

    // ---- epilogue ----
#pragma unroll
    for (int mt = 0; mt < 4; mt++) {
#pragma unroll
        for (int nt = 0; nt < 4; nt++) {
            float* a = acc[mt][nt];
            if (scale) {
                a[0] *= QSCALE; a[1] *= QSCALE; a[2] *= QSCALE; a[3] *= QSCALE;
            }
            int row0 = m0 + wm * 64 + mt * 16 + g;
            int col  = n0 + wn * 32 + nt * 8 + 2 * t;
            if (HEADOUT) {
                int h  = col >> 6;
                int dk = col & 63;
                int b0_ = row0 >> 12;
                int s0 = row0 & (SS - 1);
                float* p0 = Out + (((size_t)(b0_ * HH + h) * SS + s0) * DKK) + dk;
                *(float2*)p0 = make_float2(a[0], a[1]);
                int row1 = row0 + 8;
                int b1_ = row1 >> 12;
                int s1 = row1 & (SS - 1);
                float* p1 = Out + (((size_t)(b1_ * HH + h) * SS + s1) * DKK) + dk;
                *(float2*)p1 = make_float2(a[2], a[3]);
            } else {
                *(float2*)&Out[(size_t)row0 * DD + col] = make_float2(a[0], a[1]);
                *(float2*)&Out[(size_t)(row0 + 8) * DD + col] = make_float2(a[2], a[3]);
            }
        }
    }
}

// ---------------------------------------------------------------------------
// Flash attention v3: ldmatrix fragment loads, register-resident state.
// Block = 128 queries, 8 warps (16 q each). KV tile = 64 keys.
// K stored (key,d); V stored (d,key) transposed with conflict-free STS.
// ---------------------------------------------------------------------------
#define LDK 68   // rows 272B: LDSM banks 4r+c conflict-free
#define LDV 72   // rows 288B: LDSM banks 8r+c conflict-free (8 rows)
#define LDQ 68

__global__ __launch_bounds__(256) void flash3_kernel(
    const float* __restrict__ Qh, const float* __restrict__ Kh,
    const float* __restrict__ Vh, const int* __restrict__ kidx,
    const int* __restrict__ kcnt, float* __restrict__ AO)
{
    extern __shared__ float sm[];
    float* Ksm = sm;                    // 64 x LDK  (key, d)
    float* Vsm = Ksm + 64 * LDK;        // 64 x LDV  (d, key) transposed
    float* Psm = Vsm + 64 * LDV;        // 128 x LDQ (Q staging, then per-warp P)

    const int q0 = blockIdx.x * 128;
    const int h  = blockIdx.y;
    const int b  = blockIdx.z;
    const int tid  = threadIdx.x;
    const int lane = tid & 31;
    const int w    = tid >> 5;
    const int t    = lane & 3;    // thread in group
    const int L = kcnt[b];
    const int* idx = kidx + (size_t)b * SS;
    const size_t headbase = (size_t)(b * HH + h) * SS * DKK;
    float* Pw = Psm + w * 16 * LDQ;

    // ldmatrix per-lane offsets
    const int lm = lane >> 3, lr = lane & 7;
    const uint32_t offA_P = (uint32_t)(((lm & 1) * 8 + lr) * LDQ + (lm >> 1) * 4);
    const uint32_t offB_K = (uint32_t)(((lm >> 1) * 8 + lr) * LDK + (lm & 1) * 4);
    const uint32_t offB_V = (uint32_t)(((lm >> 1) * 8 + lr) * LDV + (lm & 1) * 4);
    const uint32_t addrP = smem_u32(Pw) + offA_P * 4;
    const uint32_t addrK = smem_u32(Ksm) + offB_K * 4;
    const uint32_t addrV = smem_u32(Vsm) + offB_V * 4;

    // ---- Stage Q tile (already scaled; convert to tf32 once) ----
#pragma unroll 2
    for (int i = tid; i < 128 * 16; i += 256) {
        int r = i >> 4, c4 = i & 15;
        float4 v = *(const float4*)&Qh[headbase + (size_t)(q0 + r) * DKK + c4 * 4];
        v.x = f2tf(v.x); v.y = f2tf(v.y); v.z = f2tf(v.z); v.w = f2tf(v.w);
        *(float4*)&Psm[r * LDQ + c4 * 4] = v;
    }
    __syncthreads();

    // ---- Load Q fragments via ldmatrix.x4: 8 k-steps ----
    uint32_t qa[8][4];
#pragma unroll
    for (int ks = 0; ks < 8; ks++)
        ldsm_x4(qa[ks], addrP + (uint32_t)(ks * 8 * 4));

    float oacc[8][4];
#pragma unroll
    for (int nt = 0; nt < 8; nt++)
#pragma unroll
        for (int e = 0; e < 4; e++) oacc[nt][e] = 0.0f;
    float m0 = -1e30f, m1 = -1e30f, l0 = 0.0f, l1 = 0.0f;

    const int nkt = (L + 63) >> 6;
    for (int kt = 0; kt < nkt; kt++) {
        const int kbase = kt * 64;
        __syncthreads();   // previous tile's compute done before overwrite

        // ---- Gather K tile (key,d) row-major ----
#pragma unroll 2
        for (int i = tid; i < 64 * 16; i += 256) {
            int j = i >> 4, c4 = i & 15;
            int gk = kbase + j;
            float4 kv = make_float4(0.f, 0.f, 0.f, 0.f);
            if (gk < L) {
                int row = idx[gk];
                kv = *(const float4*)&Kh[headbase + (size_t)row * DKK + c4 * 4];
            }
            kv.x = f2tf(kv.x); kv.y = f2tf(kv.y); kv.z = f2tf(kv.z); kv.w = f2tf(kv.w);
            *(float4*)&Ksm[j * LDK + c4 * 4] = kv;
        }
        // ---- Gather V tile transposed (d,key); swizzled index: conflict-free ----
#pragma unroll 2
        for (int i = tid; i < 64 * 16; i += 256) {
            int j = i & 63;        // key (lane-distinct -> STS banks distinct)
            int c4 = i >> 6;       // d-quad
            int gk = kbase + j;
            float4 vv = make_float4(0.f, 0.f, 0.f, 0.f);
            if (gk < L) {
                int row = idx[gk];
                vv = *(const float4*)&Vh[headbase + (size_t)row * DKK + c4 * 4];
            }
            int d = c4 * 4;
            Vsm[(d + 0) * LDV + j] = f2tf(vv.x);
            Vsm[(d + 1) * LDV + j] = f2tf(vv.y);
            Vsm[(d + 2) * LDV + j] = f2tf(vv.z);
            Vsm[(d + 3) * LDV + j] = f2tf(vv.w);
        }
        __syncthreads();

        // ---- S = Q K^T : ldmatrix x4 fetches 2 B-frags at once ----
        float sacc[8][4];
#pragma unroll
        for (int nt = 0; nt < 8; nt++)
#pragma unroll
            for (int e = 0; e < 4; e++) sacc[nt][e] = 0.0f;

#pragma unroll
        for (int ks = 0; ks < 8; ks++) {
#pragma unroll
            for (int np = 0; np < 4; np++) {
                uint32_t bb[4];
                ldsm_x4(bb, addrK + (uint32_t)((np * 16 * LDK + ks * 8) * 4));
                mma_tf32(sacc[2 * np],     qa[ks], bb[0], bb[1]);
                mma_tf32(sacc[2 * np + 1], qa[ks], bb[2], bb[3]);
            }
        }

        // ---- mask tail columns ----
        if (kbase + 64 > L) {
#pragma unroll
            for (int nt = 0; nt < 8; nt++) {
                int c0 = kbase + nt * 8 + 2 * t;
                if (c0 >= L)     { sacc[nt][0] = -1e30f; sacc[nt][2] = -1e30f; }
                if (c0 + 1 >= L) { sacc[nt][1] = -1e30f; sacc[nt][3] = -1e30f; }
            }
        }

        // ---- online softmax (log2 domain) ----
        float tm0 = -1e30f, tm1 = -1e30f;
#pragma unroll
        for (int nt = 0; nt < 8; nt++) {
            tm0 = fmaxf(tm0, fmaxf(sacc[nt][0], sacc[nt][1]));
            tm1 = fmaxf(tm1, fmaxf(sacc[nt][2], sacc[nt][3]));
        }
        tm0 = fmaxf(tm0, __shfl_xor_sync(0xffffffffu, tm0, 1));
        tm0 = fmaxf(tm0, __shfl_xor_sync(0xffffffffu, tm0, 2));
        tm1 = fmaxf(tm1, __shfl_xor_sync(0xffffffffu, tm1, 1));
        tm1 = fmaxf(tm1, __shfl_xor_sync(0xffffffffu, tm1, 2));

        float mn0 = fmaxf(m0, tm0), mn1 = fmaxf(m1, tm1);
        float al0 = exp2f(m0 - mn0), al1 = exp2f(m1 - mn1);
        float ps0 = 0.f, ps1 = 0.f;
#pragma unroll
        for (int nt = 0; nt < 8; nt++) {
            sacc[nt][0] = exp2f(sacc[nt][0] - mn0);
            sacc[nt][1] = exp2f(sacc[nt][1] - mn0);
            sacc[nt][2] = exp2f(sacc[nt][2] - mn1);
            sacc[nt][3] = exp2f(sacc[nt][3] - mn1);
            ps0 += sacc[nt][0] + sacc[nt][1];
            ps1 += sacc[nt][2] + sacc[nt][3];
        }
        ps0 += __shfl_xor_sync(0xffffffffu, ps0, 1);
        ps0 += __shfl_xor_sync(0xffffffffu, ps0, 2);
        ps1 += __shfl_xor_sync(0xffffffffu, ps1, 1);
        ps1 += __shfl_xor_sync(0xffffffffu, ps1, 2);
        l0 = l0 * al0 + ps0;  m0 = mn0;
        l1 = l1 * al1 + ps1;  m1 = mn1;

#pragma unroll
        for (int nt = 0; nt < 8; nt++) {
            oacc[nt][0] *= al0; oacc[nt][1] *= al0;
            oacc[nt][2] *= al1; oacc[nt][3] *= al1;
        }

        // ---- P C-layout -> warp-private shared (as tf32) ----
        {
            int gg = lane >> 2;
#pragma unroll
            for (int nt = 0; nt < 8; nt++) {
                float2 p01 = make_float2(f2tf(sacc[nt][0]), f2tf(sacc[nt][1]));
                float2 p23 = make_float2(f2tf(sacc[nt][2]), f2tf(sacc[nt][3]));
                *(float2*)&Pw[gg * LDQ + nt * 8 + 2 * t] = p01;
                *(float2*)&Pw[(gg + 8) * LDQ + nt * 8 + 2 * t] = p23;
            }
        }
        __syncwarp();

        // ---- O += P V : A=P (ldmatrix), B=V (ldmatrix, (d,key) layout) ----
#pragma unroll
        for (int ks = 0; ks < 8; ks++) {
            uint32_t pa[4];
            ldsm_x4(pa, addrP + (uint32_t)(ks * 8 * 4));
#pragma unroll
            for (int np = 0; np < 4; np++) {
                uint32_t bb[4];
                ldsm_x4(bb, addrV + (uint32_t)((np * 16 * LDV + ks * 8) * 4));
                mma_tf32(oacc[2 * np],     pa, bb[0], bb[1]);
                mma_tf32(oacc[2 * np + 1], pa, bb[2], bb[3]);
            }
        }
        __syncwarp();   // P reads done before next iteration's P writes
    }

    // ---- Epilogue: normalize, store to AO [b][s][h*64+dk] ----
    float inv0 = (l0 > 0.f) ? (1.0f / l0) : 0.0f;
    float inv1 = (l1 > 0.f) ? (1.0f / l1) : 0.0f;
    int gg = lane >> 2;
    int qr0 = q0 + w * 16 + gg;
    size_t base0 = ((size_t)b * SS + qr0) * DD + h * DKK;
    size_t base1 = base0 + (size_t)8 * DD;
#pragma unroll
    for (int nt = 0; nt < 8; nt++) {
        *(float2*)&AO[base0 + nt * 8 + 2 * t] =
            make_float2(oacc[nt][0] * inv0, oacc[nt][1] * inv0);
        *(float2*)&AO[base1 + nt * 8 + 2 * t] =
            make_float2(oacc[nt][2] * inv1, oacc[nt][3] * inv1);
    }
}

// ---------------------------------------------------------------------------
// Launch
// ---------------------------------------------------------------------------
extern "C" void kernel_launch(void* const* d_in, const int* in_sizes, int n_in,
                              void* d_out, int out_size)
{
    const float* q    = (const float*)d_in[0];
    const float* k    = (const float*)d_in[1];
    const float* v    = (const float*)d_in[2];
    const int*   mask = (const int*)d_in[3];
    const float* Wq   = (const float*)d_in[4];
    const float* Wk   = (const float*)d_in[5];
    const float* Wv   = (const float*)d_in[6];
    const float* Wo   = (const float*)d_in[7];
    float* out = (float*)d_out;

    float *Qh, *Kh, *Vh, *AO;
    int *kidx, *kcnt;
    cudaGetSymbolAddress((void**)&Qh, g_Qh);
    cudaGetSymbolAddress((void**)&Kh, g_Kh);
    cudaGetSymbolAddress((void**)&Vh, g_Vh);
    cudaGetSymbolAddress((void**)&AO, g_AO);
    cudaGetSymbolAddress((void**)&kidx, g_kidx);
    cudaGetSymbolAddress((void**)&kcnt, g_kcnt);

    const int gsmem = 2 * G_STAGE * (int)sizeof(float);   // 73,728 B
    cudaFuncSetAttribute(gemm3_kernel<true>,
                         cudaFuncAttributeMaxDynamicSharedMemorySize, gsmem);
    cudaFuncSetAttribute(gemm3_kernel<false>,
                         cudaFuncAttributeMaxDynamicSharedMemorySize, gsmem);

    const int fsmem = (64 * LDK + 64 * LDV + 128 * LDQ) * (int)sizeof(float);
    cudaFuncSetAttribute(flash3_kernel,
                         cudaFuncAttributeMaxDynamicSharedMemorySize, fsmem);

    compact_mask_kernel<<<BB, 32>>>(mask);

    // Fused Q/K/V projections: grid.z selects input/weight/output
    dim3 gproj(MTOT / G_BM, DD / G_BN, 3);   // (64, 4, 3)
    gemm3_kernel<true><<<gproj, 256, gsmem>>>(q, Wq, Qh, k, Wk, Kh, v, Wv, Vh);

    dim3 gflash(SS / 128, HH, BB);
    flash3_kernel<<<gflash, 256, fsmem>>>(Qh, Kh, Vh,
                                          (const int*)kidx, (const int*)kcnt, AO);

    // Output projection
    dim3 gout(MTOT / G_BM, DD / G_BN, 1);
    gemm3_kernel<false><<<gout, 256, gsmem>>>(AO, Wo, out, AO, Wo, out, AO, Wo, out);
}

// round 8
// speedup vs baseline: 1.2383x; 1.2383x over previous
#include <cuda_runtime.h>
#include <cuda_bf16.h>
#include <mma.h>
#include <cstdint>

// Problem constants
#define BB 2
#define SS 4096
#define DD 512
#define HH 8
#define DKK 64
#define MTOT (BB * SS)   // 8192

// scale folded into Q projection: 1/sqrt(64) * log2(e)
#define QSCALE 0.18033688011112042f

// ---------------------------------------------------------------------------
// Scratch (device globals; no allocation allowed)
// ---------------------------------------------------------------------------
__device__ float g_Qh[BB * HH * SS * DKK];   // [b][h][s][dk]
__device__ float g_Kh[BB * HH * SS * DKK];
__device__ float g_Vh[BB * HH * SS * DKK];
__device__ float g_AO[BB * SS * DD];         // [b][s][h*64+dk]
__device__ int   g_kidx[BB * SS];
__device__ int   g_kcnt[BB];

// ---------------------------------------------------------------------------
// Mask compaction (stable, deterministic)
// ---------------------------------------------------------------------------
__global__ void compact_mask_kernel(const int* __restrict__ mask) {
    int b = blockIdx.x;
    const int* mb = mask + b * SS;
    int lane = threadIdx.x;  // 32 threads
    int base = 0;
    for (int c = 0; c < SS; c += 32) {
        int v = (mb[c + lane] != 0);
        unsigned bal = __ballot_sync(0xffffffffu, v);
        int pos = base + __popc(bal & ((1u << lane) - 1u));
        if (v) g_kidx[b * SS + pos] = c + lane;
        base += __popc(bal);
    }
    if (lane == 0) g_kcnt[b] = base;
}

// ---------------------------------------------------------------------------
// Helpers
// ---------------------------------------------------------------------------
__device__ __forceinline__ float f2tf(float x) {
    uint32_t u;
    asm("cvt.rna.tf32.f32 %0, %1;" : "=r"(u) : "f"(x));
    return __uint_as_float(u);
}

__device__ __forceinline__ uint32_t f2tfu(float x) {
    uint32_t u;
    asm("cvt.rna.tf32.f32 %0, %1;" : "=r"(u) : "f"(x));
    return u;
}

__device__ __forceinline__ void mma_tf32(float* c, const uint32_t* a,
                                         uint32_t b0, uint32_t b1) {
    asm volatile(
        "mma.sync.aligned.m16n8k8.row.col.f32.tf32.tf32.f32 "
        "{%0,%1,%2,%3}, {%4,%5,%6,%7}, {%8,%9}, {%0,%1,%2,%3};\n"
        : "+f"(c[0]), "+f"(c[1]), "+f"(c[2]), "+f"(c[3])
        : "r"(a[0]), "r"(a[1]), "r"(a[2]), "r"(a[3]), "r"(b0), "r"(b1));
}

__device__ __forceinline__ void ldsm_x4(uint32_t* d, uint32_t saddr) {
    asm volatile(
        "ldmatrix.sync.aligned.m8n8.x4.shared.b16 {%0,%1,%2,%3}, [%4];"
        : "=r"(d[0]), "=r"(d[1]), "=r"(d[2]), "=r"(d[3]) : "r"(saddr));
}

__device__ __forceinline__ void cp_async16(float* smem_dst, const float* gsrc) {
    unsigned sa = (unsigned)__cvta_generic_to_shared(smem_dst);
    asm volatile("cp.async.cg.shared.global [%0], [%1], 16;" :: "r"(sa), "l"(gsrc));
}

__device__ __forceinline__ uint32_t smem_u32(const void* p) {
    return (uint32_t)__cvta_generic_to_shared(p);
}

// ---------------------------------------------------------------------------
// Fused QKV GEMM (unchanged from round 6 — measured 53.8us/launch).
// C[M,512] = X[M,512] @ W^T, mma.m16n8k8 tf32, cp.async double-buffered,
// ldmatrix fragment loads. grid.z selects (q/k/v).
// ---------------------------------------------------------------------------
#define G_BM 128
#define G_BN 128
#define G_BK 32
#define G_LDA 36
#define G_STAGE (G_BM * G_LDA + G_BN * G_LDA)
#define G_NIT (DD / G_BK)   // 16

template <bool HEADOUT>
__global__ __launch_bounds__(256, 2) void gemm3_kernel(
    const float* __restrict__ X0, const float* __restrict__ W0,
    float* __restrict__ O0,
    const float* __restrict__ X1, const float* __restrict__ W1,
    float* __restrict__ O1,
    const float* __restrict__ X2, const float* __restrict__ W2,
    float* __restrict__ O2)
{
    extern __shared__ float smem[];

    const int z = blockIdx.z;
    const float* X = (z == 0) ? X0 : (z == 1) ? X1 : X2;
    const float* W = (z == 0) ? W0 : (z == 1) ? W1 : W2;
    float*     Out = (z == 0) ? O0 : (z == 1) ? O1 : O2;
    const bool scale = HEADOUT && (z == 0);

    const int m0 = blockIdx.x * G_BM;
    const int n0 = blockIdx.y * G_BN;
    const int tid  = threadIdx.x;
    const int lane = tid & 31;
    const int w    = tid >> 5;
    const int g    = lane >> 2;
    const int t    = lane & 3;
    const int wm   = w >> 2;
    const int wn   = w & 3;

    const int lm = lane >> 3, lr = lane & 7;
    const uint32_t offA = (uint32_t)(((lm & 1) * 8 + lr) * G_LDA + (lm >> 1) * 4);
    const uint32_t offB = (uint32_t)(((lm >> 1) * 8 + lr) * G_LDA + (lm & 1) * 4);

    float acc[4][4][4];
#pragma unroll
    for (int mt = 0; mt < 4; mt++)
#pragma unroll
        for (int nt = 0; nt < 4; nt++)
#pragma unroll
            for (int e = 0; e < 4; e++) acc[mt][nt][e] = 0.0f;

    auto load_stage = [&](int s, int k0) {
        float* As = smem + s * G_STAGE;
        float* Bs = As + G_BM * G_LDA;
#pragma unroll
        for (int j = 0; j < 4; j++) {
            int idx = tid * 4 + j;
            int r = idx >> 3, seg = idx & 7;
            cp_async16(&As[r * G_LDA + seg * 4],
                       &X[(size_t)(m0 + r) * DD + k0 + seg * 4]);
            cp_async16(&Bs[r * G_LDA + seg * 4],
                       &W[(size_t)(n0 + r) * DD + k0 + seg * 4]);
        }
        asm volatile("cp.async.commit_group;" ::: "memory");
    };

    load_stage(0, 0);

    for (int it = 0; it < G_NIT; it++) {
        asm volatile("cp.async.wait_group 0;" ::: "memory");
        __syncthreads();
        if (it + 1 < G_NIT) load_stage((it + 1) & 1, (it + 1) * G_BK);

        const float* As = smem + (it & 1) * G_STAGE;
        const float* Bs = As + G_BM * G_LDA;
        const uint32_t aBase = smem_u32(As) + offA * 4;
        const uint32_t bBase = smem_u32(Bs) + offB * 4;

#pragma unroll
        for (int ks = 0; ks < 4; ks++) {
            uint32_t af[4][4];
            uint32_t bf[4][2];
#pragma unroll
            for (int mt = 0; mt < 4; mt++) {
                ldsm_x4(af[mt], aBase + (uint32_t)(((wm * 64 + mt * 16) * G_LDA + ks * 8) * 4));
#pragma unroll
                for (int e = 0; e < 4; e++)
                    af[mt][e] = f2tfu(__uint_as_float(af[mt][e]));
            }
#pragma unroll
            for (int np = 0; np < 2; np++) {
                uint32_t bb[4];
                ldsm_x4(bb, bBase + (uint32_t)(((wn * 32 + np * 16) * G_LDA + ks * 8) * 4));
#pragma unroll
                for (int e = 0; e < 4; e++)
                    bb[e] = f2tfu(__uint_as_float(bb[e]));
                bf[2 * np][0] = bb[0]; bf[2 * np][1] = bb[1];
                bf[2 * np + 1][0] = bb[2]; bf[2 * np + 1][1] = bb[3];
            }
#pragma unroll
            for (int mt = 0; mt < 4; mt++)
#pragma unroll
                for (int nt = 0; nt < 4; nt++)
                    mma_tf32(acc[mt][nt], af[mt], bf[nt][0], bf[nt][1]);
        }
        __syncthreads();
    }

#pragma unroll
    for (int mt = 0; mt < 4; mt++) {
#pragma unroll
        for (int nt = 0; nt < 4; nt++) {
            float* a = acc[mt][nt];
            if (scale) {
                a[0] *= QSCALE; a[1] *= QSCALE; a[2] *= QSCALE; a[3] *= QSCALE;
            }
            int row0 = m0 + wm * 64 + mt * 16 + g;
            int col  = n0 + wn * 32 + nt * 8 + 2 * t;
            if (HEADOUT) {
                int h  = col >> 6;
                int dk = col & 63;
                int b0_ = row0 >> 12;
                int s0 = row0 & (SS - 1);
                float* p0 = Out + (((size_t)(b0_ * HH + h) * SS + s0) * DKK) + dk;
                *(float2*)p0 = make_float2(a[0], a[1]);
                int row1 = row0 + 8;
                int b1_ = row1 >> 12;
                int s1 = row1 & (SS - 1);
                float* p1 = Out + (((size_t)(b1_ * HH + h) * SS + s1) * DKK) + dk;
                *(float2*)p1 = make_float2(a[2], a[3]);
            } else {
                *(float2*)&Out[(size_t)row0 * DD + col] = make_float2(a[0], a[1]);
                *(float2*)&Out[(size_t)(row0 + 8) * DD + col] = make_float2(a[2], a[3]);
            }
        }
    }
}

// ---------------------------------------------------------------------------
// Flash attention v4: flash2 layouts (K,V row-major, coalesced fused gather)
// + ldmatrix for K B-fragments and Q/P A-fragments only. V stays scalar LDS
// (conflict-free banks 8t+g+8nt), avoiding the transpose that sank flash3.
// ---------------------------------------------------------------------------
#define LDK 68   // 17 x 16B rows: LDSM phase-conflict-free
#define LDV 72   // scalar V reads: banks (8t+g) distinct
#define LDQ 68

__global__ __launch_bounds__(256) void flash4_kernel(
    const float* __restrict__ Qh, const float* __restrict__ Kh,
    const float* __restrict__ Vh, const int* __restrict__ kidx,
    const int* __restrict__ kcnt, float* __restrict__ AO)
{
    extern __shared__ float sm[];
    float* Ksm = sm;                    // 64 x LDK  (key, d)
    float* Vsm = Ksm + 64 * LDK;        // 64 x LDV  (key, d)
    float* Psm = Vsm + 64 * LDV;        // 128 x LDQ (Q staging, then per-warp P)

    const int q0 = blockIdx.x * 128;
    const int h  = blockIdx.y;
    const int b  = blockIdx.z;
    const int tid  = threadIdx.x;
    const int lane = tid & 31;
    const int w    = tid >> 5;
    const int g    = lane >> 2;
    const int t    = lane & 3;
    const int L = kcnt[b];
    const int* idx = kidx + (size_t)b * SS;
    const size_t headbase = (size_t)(b * HH + h) * SS * DKK;
    float* Pw = Psm + w * 16 * LDQ;

    // ldmatrix per-lane offsets (elements)
    const int lm = lane >> 3, lr = lane & 7;
    const uint32_t offA_P = (uint32_t)(((lm & 1) * 8 + lr) * LDQ + (lm >> 1) * 4);
    const uint32_t offB_K = (uint32_t)(((lm >> 1) * 8 + lr) * LDK + (lm & 1) * 4);
    const uint32_t addrP = smem_u32(Pw) + offA_P * 4;
    const uint32_t addrK = smem_u32(Ksm) + offB_K * 4;

    // ---- Stage Q tile (already scaled; convert to tf32 once) ----
#pragma unroll 2
    for (int i = tid; i < 128 * 16; i += 256) {
        int r = i >> 4, c4 = i & 15;
        float4 v = *(const float4*)&Qh[headbase + (size_t)(q0 + r) * DKK + c4 * 4];
        v.x = f2tf(v.x); v.y = f2tf(v.y); v.z = f2tf(v.z); v.w = f2tf(v.w);
        *(float4*)&Psm[r * LDQ + c4 * 4] = v;
    }
    __syncthreads();

    // ---- Load Q fragments via ldmatrix.x4: 8 k-steps ----
    uint32_t qa[8][4];
#pragma unroll
    for (int ks = 0; ks < 8; ks++)
        ldsm_x4(qa[ks], addrP + (uint32_t)(ks * 8 * 4));

    float oacc[8][4];
#pragma unroll
    for (int nt = 0; nt < 8; nt++)
#pragma unroll
        for (int e = 0; e < 4; e++) oacc[nt][e] = 0.0f;
    float m0 = -1e30f, m1 = -1e30f, l0 = 0.0f, l1 = 0.0f;

    const int nkt = (L + 63) >> 6;
    for (int kt = 0; kt < nkt; kt++) {
        const int kbase = kt * 64;
        __syncthreads();   // previous tile's compute done before overwrite

        // ---- Fused coalesced K/V gather (both row-major), tf32 convert ----
#pragma unroll 2
        for (int i = tid; i < 64 * 16; i += 256) {
            int j = i >> 4, c4 = i & 15;
            int gk = kbase + j;
            float4 kv = make_float4(0.f, 0.f, 0.f, 0.f);
            float4 vv = kv;
            if (gk < L) {
                int row = idx[gk];
                kv = *(const float4*)&Kh[headbase + (size_t)row * DKK + c4 * 4];
                vv = *(const float4*)&Vh[headbase + (size_t)row * DKK + c4 * 4];
            }
            kv.x = f2tf(kv.x); kv.y = f2tf(kv.y); kv.z = f2tf(kv.z); kv.w = f2tf(kv.w);
            vv.x = f2tf(vv.x); vv.y = f2tf(vv.y); vv.z = f2tf(vv.z); vv.w = f2tf(vv.w);
            *(float4*)&Ksm[j * LDK + c4 * 4] = kv;
            *(float4*)&Vsm[j * LDV + c4 * 4] = vv;
        }
        __syncthreads();

        // ---- S = Q K^T : K B-fragments via ldmatrix (2 frags per x4) ----
        float sacc[8][4];
#pragma unroll
        for (int nt = 0; nt < 8; nt++)
#pragma unroll
            for (int e = 0; e < 4; e++) sacc[nt][e] = 0.0f;

#pragma unroll
        for (int ks = 0; ks < 8; ks++) {
#pragma unroll
            for (int np = 0; np < 4; np++) {
                uint32_t bb[4];
                ldsm_x4(bb, addrK + (uint32_t)((np * 16 * LDK + ks * 8) * 4));
                mma_tf32(sacc[2 * np],     qa[ks], bb[0], bb[1]);
                mma_tf32(sacc[2 * np + 1], qa[ks], bb[2], bb[3]);
            }
        }

        // ---- mask tail columns ----
        if (kbase + 64 > L) {
#pragma unroll
            for (int nt = 0; nt < 8; nt++) {
                int c0 = kbase + nt * 8 + 2 * t;
                if (c0 >= L)     { sacc[nt][0] = -1e30f; sacc[nt][2] = -1e30f; }
                if (c0 + 1 >= L) { sacc[nt][1] = -1e30f; sacc[nt][3] = -1e30f; }
            }
        }

        // ---- online softmax (log2 domain) ----
        float tm0 = -1e30f, tm1 = -1e30f;
#pragma unroll
        for (int nt = 0; nt < 8; nt++) {
            tm0 = fmaxf(tm0, fmaxf(sacc[nt][0], sacc[nt][1]));
            tm1 = fmaxf(tm1, fmaxf(sacc[nt][2], sacc[nt][3]));
        }
        tm0 = fmaxf(tm0, __shfl_xor_sync(0xffffffffu, tm0, 1));
        tm0 = fmaxf(tm0, __shfl_xor_sync(0xffffffffu, tm0, 2));
        tm1 = fmaxf(tm1, __shfl_xor_sync(0xffffffffu, tm1, 1));
        tm1 = fmaxf(tm1, __shfl_xor_sync(0xffffffffu, tm1, 2));

        float mn0 = fmaxf(m0, tm0), mn1 = fmaxf(m1, tm1);
        float al0 = exp2f(m0 - mn0), al1 = exp2f(m1 - mn1);
        float ps0 = 0.f, ps1 = 0.f;
#pragma unroll
        for (int nt = 0; nt < 8; nt++) {
            sacc[nt][0] = exp2f(sacc[nt][0] - mn0);
            sacc[nt][1] = exp2f(sacc[nt][1] - mn0);
            sacc[nt][2] = exp2f(sacc[nt][2] - mn1);
            sacc[nt][3] = exp2f(sacc[nt][3] - mn1);
            ps0 += sacc[nt][0] + sacc[nt][1];
            ps1 += sacc[nt][2] + sacc[nt][3];
        }
        ps0 += __shfl_xor_sync(0xffffffffu, ps0, 1);
        ps0 += __shfl_xor_sync(0xffffffffu, ps0, 2);
        ps1 += __shfl_xor_sync(0xffffffffu, ps1, 1);
        ps1 += __shfl_xor_sync(0xffffffffu, ps1, 2);
        l0 = l0 * al0 + ps0;  m0 = mn0;
        l1 = l1 * al1 + ps1;  m1 = mn1;

#pragma unroll
        for (int nt = 0; nt < 8; nt++) {
            oacc[nt][0] *= al0; oacc[nt][1] *= al0;
            oacc[nt][2] *= al1; oacc[nt][3] *= al1;
        }

        // ---- P C-layout -> warp-private shared (as tf32) ----
#pragma unroll
        for (int nt = 0; nt < 8; nt++) {
            float2 p01 = make_float2(f2tf(sacc[nt][0]), f2tf(sacc[nt][1]));
            float2 p23 = make_float2(f2tf(sacc[nt][2]), f2tf(sacc[nt][3]));
            *(float2*)&Pw[g * LDQ + nt * 8 + 2 * t] = p01;
            *(float2*)&Pw[(g + 8) * LDQ + nt * 8 + 2 * t] = p23;
        }
        __syncwarp();

        // ---- O += P V : P via ldmatrix, V scalar (row-major, conflict-free) ----
#pragma unroll
        for (int ks = 0; ks < 8; ks++) {
            uint32_t pa[4];
            ldsm_x4(pa, addrP + (uint32_t)(ks * 8 * 4));
#pragma unroll
            for (int nt = 0; nt < 8; nt++) {
                uint32_t b0 = __float_as_uint(Vsm[(ks * 8 + t) * LDV + nt * 8 + g]);
                uint32_t b1 = __float_as_uint(Vsm[(ks * 8 + t + 4) * LDV + nt * 8 + g]);
                mma_tf32(oacc[nt], pa, b0, b1);
            }
        }
        __syncwarp();   // P reads done before next iteration's P writes
    }

    // ---- Epilogue: normalize, store to AO [b][s][h*64+dk] ----
    float inv0 = (l0 > 0.f) ? (1.0f / l0) : 0.0f;
    float inv1 = (l1 > 0.f) ? (1.0f / l1) : 0.0f;
    int qr0 = q0 + w * 16 + g;
    size_t base0 = ((size_t)b * SS + qr0) * DD + h * DKK;
    size_t base1 = base0 + (size_t)8 * DD;
#pragma unroll
    for (int nt = 0; nt < 8; nt++) {
        *(float2*)&AO[base0 + nt * 8 + 2 * t] =
            make_float2(oacc[nt][0] * inv0, oacc[nt][1] * inv0);
        *(float2*)&AO[base1 + nt * 8 + 2 * t] =
            make_float2(oacc[nt][2] * inv1, oacc[nt][3] * inv1);
    }
}

// ---------------------------------------------------------------------------
// Launch
// ---------------------------------------------------------------------------
extern "C" void kernel_launch(void* const* d_in, const int* in_sizes, int n_in,
                              void* d_out, int out_size)
{
    const float* q    = (const float*)d_in[0];
    const float* k    = (const float*)d_in[1];
    const float* v    = (const float*)d_in[2];
    const int*   mask = (const int*)d_in[3];
    const float* Wq   = (const float*)d_in[4];
    const float* Wk   = (const float*)d_in[5];
    const float* Wv   = (const float*)d_in[6];
    const float* Wo   = (const float*)d_in[7];
    float* out = (float*)d_out;

    float *Qh, *Kh, *Vh, *AO;
    int *kidx, *kcnt;
    cudaGetSymbolAddress((void**)&Qh, g_Qh);
    cudaGetSymbolAddress((void**)&Kh, g_Kh);
    cudaGetSymbolAddress((void**)&Vh, g_Vh);
    cudaGetSymbolAddress((void**)&AO, g_AO);
    cudaGetSymbolAddress((void**)&kidx, g_kidx);
    cudaGetSymbolAddress((void**)&kcnt, g_kcnt);

    const int gsmem = 2 * G_STAGE * (int)sizeof(float);   // 73,728 B
    cudaFuncSetAttribute(gemm3_kernel<true>,
                         cudaFuncAttributeMaxDynamicSharedMemorySize, gsmem);
    cudaFuncSetAttribute(gemm3_kernel<false>,
                         cudaFuncAttributeMaxDynamicSharedMemorySize, gsmem);

    const int fsmem = (64 * LDK + 64 * LDV + 128 * LDQ) * (int)sizeof(float);
    cudaFuncSetAttribute(flash4_kernel,
                         cudaFuncAttributeMaxDynamicSharedMemorySize, fsmem);

    compact_mask_kernel<<<BB, 32>>>(mask);

    // Fused Q/K/V projections: grid.z selects input/weight/output
    dim3 gproj(MTOT / G_BM, DD / G_BN, 3);   // (64, 4, 3)
    gemm3_kernel<true><<<gproj, 256, gsmem>>>(q, Wq, Qh, k, Wk, Kh, v, Wv, Vh);

    dim3 gflash(SS / 128, HH, BB);
    flash4_kernel<<<gflash, 256, fsmem>>>(Qh, Kh, Vh,
                                          (const int*)kidx, (const int*)kcnt, AO);

    // Output projection
    dim3 gout(MTOT / G_BM, DD / G_BN, 1);
    gemm3_kernel<false><<<gout, 256, gsmem>>>(AO, Wo, out, AO, Wo, out, AO, Wo, out);
}

// round 9
// speedup vs baseline: 1.2387x; 1.0003x over previous
#include <cuda_runtime.h>
#include <cuda_bf16.h>
#include <mma.h>
#include <cstdint>

// Problem constants
#define BB 2
#define SS 4096
#define DD 512
#define HH 8
#define DKK 64
#define MTOT (BB * SS)   // 8192

// scale folded into Q projection: 1/sqrt(64) * log2(e)
#define QSCALE 0.18033688011112042f

// ---------------------------------------------------------------------------
// Scratch (device globals; no allocation allowed)
// ---------------------------------------------------------------------------
__device__ float g_Qh[BB * HH * SS * DKK];   // [b][h][s][dk]
__device__ float g_Kh[BB * HH * SS * DKK];
__device__ float g_Vh[BB * HH * SS * DKK];
__device__ float g_AO[BB * SS * DD];         // [b][s][h*64+dk]
__device__ int   g_kidx[BB * SS];
__device__ int   g_kcnt[BB];

// ---------------------------------------------------------------------------
// Mask compaction (stable, deterministic)
// ---------------------------------------------------------------------------
__global__ void compact_mask_kernel(const int* __restrict__ mask) {
    int b = blockIdx.x;
    const int* mb = mask + b * SS;
    int lane = threadIdx.x;  // 32 threads
    int base = 0;
    for (int c = 0; c < SS; c += 32) {
        int v = (mb[c + lane] != 0);
        unsigned bal = __ballot_sync(0xffffffffu, v);
        int pos = base + __popc(bal & ((1u << lane) - 1u));
        if (v) g_kidx[b * SS + pos] = c + lane;
        base += __popc(bal);
    }
    if (lane == 0) g_kcnt[b] = base;
}

// ---------------------------------------------------------------------------
// Helpers
// ---------------------------------------------------------------------------
__device__ __forceinline__ float f2tf(float x) {
    uint32_t u;
    asm("cvt.rna.tf32.f32 %0, %1;" : "=r"(u) : "f"(x));
    return __uint_as_float(u);
}

__device__ __forceinline__ uint32_t f2tfu(float x) {
    uint32_t u;
    asm("cvt.rna.tf32.f32 %0, %1;" : "=r"(u) : "f"(x));
    return u;
}

__device__ __forceinline__ void mma_tf32(float* c, const uint32_t* a,
                                         uint32_t b0, uint32_t b1) {
    asm volatile(
        "mma.sync.aligned.m16n8k8.row.col.f32.tf32.tf32.f32 "
        "{%0,%1,%2,%3}, {%4,%5,%6,%7}, {%8,%9}, {%0,%1,%2,%3};\n"
        : "+f"(c[0]), "+f"(c[1]), "+f"(c[2]), "+f"(c[3])
        : "r"(a[0]), "r"(a[1]), "r"(a[2]), "r"(a[3]), "r"(b0), "r"(b1));
}

__device__ __forceinline__ void ldsm_x4(uint32_t* d, uint32_t saddr) {
    asm volatile(
        "ldmatrix.sync.aligned.m8n8.x4.shared.b16 {%0,%1,%2,%3}, [%4];"
        : "=r"(d[0]), "=r"(d[1]), "=r"(d[2]), "=r"(d[3]) : "r"(saddr));
}

__device__ __forceinline__ void cp_async16(float* smem_dst, const float* gsrc) {
    unsigned sa = (unsigned)__cvta_generic_to_shared(smem_dst);
    asm volatile("cp.async.cg.shared.global [%0], [%1], 16;" :: "r"(sa), "l"(gsrc));
}

__device__ __forceinline__ uint32_t smem_u32(const void* p) {
    return (uint32_t)__cvta_generic_to_shared(p);
}

// ---------------------------------------------------------------------------
// Fused QKV GEMM (unchanged from round 6 — measured 53.8us/launch).
// C[M,512] = X[M,512] @ W^T, mma.m16n8k8 tf32, cp.async double-buffered,
// ldmatrix fragment loads. grid.z selects (q/k/v).
// ---------------------------------------------------------------------------
#define G_BM 128
#define G_BN 128
#define G_BK 32
#define G_LDA 36
#define G_STAGE (G_BM * G_LDA + G_BN * G_LDA)
#define G_NIT (DD / G_BK)   // 16

template <bool HEADOUT>
__global__ __launch_bounds__(256, 2) void gemm3_kernel(
    const float* __restrict__ X0, const float* __restrict__ W0,
    float* __restrict__ O0,
    const float* __restrict__ X1, const float* __restrict__ W1,
    float* __restrict__ O1,
    const float* __restrict__ X2, const float* __restrict__ W2,
    float* __restrict__ O2)
{
    extern __shared__ float smem[];

    const int z = blockIdx.z;
    const float* X = (z == 0) ? X0 : (z == 1) ? X1 : X2;
    const float* W = (z == 0) ? W0 : (z == 1) ? W1 : W2;
    float*     Out = (z == 0) ? O0 : (z == 1) ? O1 : O2;
    const bool scale = HEADOUT && (z == 0);

    const int m0 = blockIdx.x * G_BM;
    const int n0 = blockIdx.y * G_BN;
    const int tid  = threadIdx.x;
    const int lane = tid & 31;
    const int w    = tid >> 5;
    const int g    = lane >> 2;
    const int t    = lane & 3;
    const int wm   = w >> 2;
    const int wn   = w & 3;

    const int lm = lane >> 3, lr = lane & 7;
    const uint32_t offA = (uint32_t)(((lm & 1) * 8 + lr) * G_LDA + (lm >> 1) * 4);
    const uint32_t offB = (uint32_t)(((lm >> 1) * 8 + lr) * G_LDA + (lm & 1) * 4);

    float acc[4][4][4];
#pragma unroll
    for (int mt = 0; mt < 4; mt++)
#pragma unroll
        for (int nt = 0; nt < 4; nt++)
#pragma unroll
            for (int e = 0; e < 4; e++) acc[mt][nt][e] = 0.0f;

    auto load_stage = [&](int s, int k0) {
        float* As = smem + s * G_STAGE;
        float* Bs = As + G_BM * G_LDA;
#pragma unroll
        for (int j = 0; j < 4; j++) {
            int idx = tid * 4 + j;
            int r = idx >> 3, seg = idx & 7;
            cp_async16(&As[r * G_LDA + seg * 4],
                       &X[(size_t)(m0 + r) * DD + k0 + seg * 4]);
            cp_async16(&Bs[r * G_LDA + seg * 4],
                       &W[(size_t)(n0 + r) * DD + k0 + seg * 4]);
        }
        asm volatile("cp.async.commit_group;" ::: "memory");
    };

    load_stage(0, 0);

    for (int it = 0; it < G_NIT; it++) {
        asm volatile("cp.async.wait_group 0;" ::: "memory");
        __syncthreads();
        if (it + 1 < G_NIT) load_stage((it + 1) & 1, (it + 1) * G_BK);

        const float* As = smem + (it & 1) * G_STAGE;
        const float* Bs = As + G_BM * G_LDA;
        const uint32_t aBase = smem_u32(As) + offA * 4;
        const uint32_t bBase = smem_u32(Bs) + offB * 4;

#pragma unroll
        for (int ks = 0; ks < 4; ks++) {
            uint32_t af[4][4];
            uint32_t bf[4][2];
#pragma unroll
            for (int mt = 0; mt < 4; mt++) {
                ldsm_x4(af[mt], aBase + (uint32_t)(((wm * 64 + mt * 16) * G_LDA + ks * 8) * 4));
#pragma unroll
                for (int e = 0; e < 4; e++)
                    af[mt][e] = f2tfu(__uint_as_float(af[mt][e]));
            }
#pragma unroll
            for (int np = 0; np < 2; np++) {
                uint32_t bb[4];
                ldsm_x4(bb, bBase + (uint32_t)(((wn * 32 + np * 16) * G_LDA + ks * 8) * 4));
#pragma unroll
                for (int e = 0; e < 4; e++)
                    bb[e] = f2tfu(__uint_as_float(bb[e]));
                bf[2 * np][0] = bb[0]; bf[2 * np][1] = bb[1];
                bf[2 * np + 1][0] = bb[2]; bf[2 * np + 1][1] = bb[3];
            }
#pragma unroll
            for (int mt = 0; mt < 4; mt++)
#pragma unroll
                for (int nt = 0; nt < 4; nt++)
                    mma_tf32(acc[mt][nt], af[mt], bf[nt][0], bf[nt][1]);
        }
        __syncthreads();
    }

#pragma unroll
    for (int mt = 0; mt < 4; mt++) {
#pragma unroll
        for (int nt = 0; nt < 4; nt++) {
            float* a = acc[mt][nt];
            if (scale) {
                a[0] *= QSCALE; a[1] *= QSCALE; a[2] *= QSCALE; a[3] *= QSCALE;
            }
            int row0 = m0 + wm * 64 + mt * 16 + g;
            int col  = n0 + wn * 32 + nt * 8 + 2 * t;
            if (HEADOUT) {
                int h  = col >> 6;
                int dk = col & 63;
                int b0_ = row0 >> 12;
                int s0 = row0 & (SS - 1);
                float* p0 = Out + (((size_t)(b0_ * HH + h) * SS + s0) * DKK) + dk;
                *(float2*)p0 = make_float2(a[0], a[1]);
                int row1 = row0 + 8;
                int b1_ = row1 >> 12;
                int s1 = row1 & (SS - 1);
                float* p1 = Out + (((size_t)(b1_ * HH + h) * SS + s1) * DKK) + dk;
                *(float2*)p1 = make_float2(a[2], a[3]);
            } else {
                *(float2*)&Out[(size_t)row0 * DD + col] = make_float2(a[0], a[1]);
                *(float2*)&Out[(size_t)(row0 + 8) * DD + col] = make_float2(a[2], a[3]);
            }
        }
    }
}

// ---------------------------------------------------------------------------
// Flash attention v4: flash2 layouts (K,V row-major, coalesced fused gather)
// + ldmatrix for K B-fragments and Q/P A-fragments only. V stays scalar LDS
// (conflict-free banks 8t+g+8nt), avoiding the transpose that sank flash3.
// ---------------------------------------------------------------------------
#define LDK 68   // 17 x 16B rows: LDSM phase-conflict-free
#define LDV 72   // scalar V reads: banks (8t+g) distinct
#define LDQ 68

__global__ __launch_bounds__(256) void flash4_kernel(
    const float* __restrict__ Qh, const float* __restrict__ Kh,
    const float* __restrict__ Vh, const int* __restrict__ kidx,
    const int* __restrict__ kcnt, float* __restrict__ AO)
{
    extern __shared__ float sm[];
    float* Ksm = sm;                    // 64 x LDK  (key, d)
    float* Vsm = Ksm + 64 * LDK;        // 64 x LDV  (key, d)
    float* Psm = Vsm + 64 * LDV;        // 128 x LDQ (Q staging, then per-warp P)

    const int q0 = blockIdx.x * 128;
    const int h  = blockIdx.y;
    const int b  = blockIdx.z;
    const int tid  = threadIdx.x;
    const int lane = tid & 31;
    const int w    = tid >> 5;
    const int g    = lane >> 2;
    const int t    = lane & 3;
    const int L = kcnt[b];
    const int* idx = kidx + (size_t)b * SS;
    const size_t headbase = (size_t)(b * HH + h) * SS * DKK;
    float* Pw = Psm + w * 16 * LDQ;

    // ldmatrix per-lane offsets (elements)
    const int lm = lane >> 3, lr = lane & 7;
    const uint32_t offA_P = (uint32_t)(((lm & 1) * 8 + lr) * LDQ + (lm >> 1) * 4);
    const uint32_t offB_K = (uint32_t)(((lm >> 1) * 8 + lr) * LDK + (lm & 1) * 4);
    const uint32_t addrP = smem_u32(Pw) + offA_P * 4;
    const uint32_t addrK = smem_u32(Ksm) + offB_K * 4;

    // ---- Stage Q tile (already scaled; convert to tf32 once) ----
#pragma unroll 2
    for (int i = tid; i < 128 * 16; i += 256) {
        int r = i >> 4, c4 = i & 15;
        float4 v = *(const float4*)&Qh[headbase + (size_t)(q0 + r) * DKK + c4 * 4];
        v.x = f2tf(v.x); v.y = f2tf(v.y); v.z = f2tf(v.z); v.w = f2tf(v.w);
        *(float4*)&Psm[r * LDQ + c4 * 4] = v;
    }
    __syncthreads();

    // ---- Load Q fragments via ldmatrix.x4: 8 k-steps ----
    uint32_t qa[8][4];
#pragma unroll
    for (int ks = 0; ks < 8; ks++)
        ldsm_x4(qa[ks], addrP + (uint32_t)(ks * 8 * 4));

    float oacc[8][4];
#pragma unroll
    for (int nt = 0; nt < 8; nt++)
#pragma unroll
        for (int e = 0; e < 4; e++) oacc[nt][e] = 0.0f;
    float m0 = -1e30f, m1 = -1e30f, l0 = 0.0f, l1 = 0.0f;

    const int nkt = (L + 63) >> 6;
    for (int kt = 0; kt < nkt; kt++) {
        const int kbase = kt * 64;
        __syncthreads();   // previous tile's compute done before overwrite

        // ---- Fused coalesced K/V gather (both row-major), tf32 convert ----
#pragma unroll 2
        for (int i = tid; i < 64 * 16; i += 256) {
            int j = i >> 4, c4 = i & 15;
            int gk = kbase + j;
            float4 kv = make_float4(0.f, 0.f, 0.f, 0.f);
            float4 vv = kv;
            if (gk < L) {
                int row = idx[gk];
                kv = *(const float4*)&Kh[headbase + (size_t)row * DKK + c4 * 4];
                vv = *(const float4*)&Vh[headbase + (size_t)row * DKK + c4 * 4];
            }
            kv.x = f2tf(kv.x); kv.y = f2tf(kv.y); kv.z = f2tf(kv.z); kv.w = f2tf(kv.w);
            vv.x = f2tf(vv.x); vv.y = f2tf(vv.y); vv.z = f2tf(vv.z); vv.w = f2tf(vv.w);
            *(float4*)&Ksm[j * LDK + c4 * 4] = kv;
            *(float4*)&Vsm[j * LDV + c4 * 4] = vv;
        }
        __syncthreads();

        // ---- S = Q K^T : K B-fragments via ldmatrix (2 frags per x4) ----
        float sacc[8][4];
#pragma unroll
        for (int nt = 0; nt < 8; nt++)
#pragma unroll
            for (int e = 0; e < 4; e++) sacc[nt][e] = 0.0f;

#pragma unroll
        for (int ks = 0; ks < 8; ks++) {
#pragma unroll
            for (int np = 0; np < 4; np++) {
                uint32_t bb[4];
                ldsm_x4(bb, addrK + (uint32_t)((np * 16 * LDK + ks * 8) * 4));
                mma_tf32(sacc[2 * np],     qa[ks], bb[0], bb[1]);
                mma_tf32(sacc[2 * np + 1], qa[ks], bb[2], bb[3]);
            }
        }

        // ---- mask tail columns ----
        if (kbase + 64 > L) {
#pragma unroll
            for (int nt = 0; nt < 8; nt++) {
                int c0 = kbase + nt * 8 + 2 * t;
                if (c0 >= L)     { sacc[nt][0] = -1e30f; sacc[nt][2] = -1e30f; }
                if (c0 + 1 >= L) { sacc[nt][1] = -1e30f; sacc[nt][3] = -1e30f; }
            }
        }

        // ---- online softmax (log2 domain) ----
        float tm0 = -1e30f, tm1 = -1e30f;
#pragma unroll
        for (int nt = 0; nt < 8; nt++) {
            tm0 = fmaxf(tm0, fmaxf(sacc[nt][0], sacc[nt][1]));
            tm1 = fmaxf(tm1, fmaxf(sacc[nt][2], sacc[nt][3]));
        }
        tm0 = fmaxf(tm0, __shfl_xor_sync(0xffffffffu, tm0, 1));
        tm0 = fmaxf(tm0, __shfl_xor_sync(0xffffffffu, tm0, 2));
        tm1 = fmaxf(tm1, __shfl_xor_sync(0xffffffffu, tm1, 1));
        tm1 = fmaxf(tm1, __shfl_xor_sync(0xffffffffu, tm1, 2));

        float mn0 = fmaxf(m0, tm0), mn1 = fmaxf(m1, tm1);
        float al0 = exp2f(m0 - mn0), al1 = exp2f(m1 - mn1);
        float ps0 = 0.f, ps1 = 0.f;
#pragma unroll
        for (int nt = 0; nt < 8; nt++) {
            sacc[nt][0] = exp2f(sacc[nt][0] - mn0);
            sacc[nt][1] = exp2f(sacc[nt][1] - mn0);
            sacc[nt][2] = exp2f(sacc[nt][2] - mn1);
            sacc[nt][3] = exp2f(sacc[nt][3] - mn1);
            ps0 += sacc[nt][0] + sacc[nt][1];
            ps1 += sacc[nt][2] + sacc[nt][3];
        }
        ps0 += __shfl_xor_sync(0xffffffffu, ps0, 1);
        ps0 += __shfl_xor_sync(0xffffffffu, ps0, 2);
        ps1 += __shfl_xor_sync(0xffffffffu, ps1, 1);
        ps1 += __shfl_xor_sync(0xffffffffu, ps1, 2);
        l0 = l0 * al0 + ps0;  m0 = mn0;
        l1 = l1 * al1 + ps1;  m1 = mn1;

#pragma unroll
        for (int nt = 0; nt < 8; nt++) {
            oacc[nt][0] *= al0; oacc[nt][1] *= al0;
            oacc[nt][2] *= al1; oacc[nt][3] *= al1;
        }

        // ---- P C-layout -> warp-private shared (as tf32) ----
#pragma unroll
        for (int nt = 0; nt < 8; nt++) {
            float2 p01 = make_float2(f2tf(sacc[nt][0]), f2tf(sacc[nt][1]));
            float2 p23 = make_float2(f2tf(sacc[nt][2]), f2tf(sacc[nt][3]));
            *(float2*)&Pw[g * LDQ + nt * 8 + 2 * t] = p01;
            *(float2*)&Pw[(g + 8) * LDQ + nt * 8 + 2 * t] = p23;
        }
        __syncwarp();

        // ---- O += P V : P via ldmatrix, V scalar (row-major, conflict-free) ----
#pragma unroll
        for (int ks = 0; ks < 8; ks++) {
            uint32_t pa[4];
            ldsm_x4(pa, addrP + (uint32_t)(ks * 8 * 4));
#pragma unroll
            for (int nt = 0; nt < 8; nt++) {
                uint32_t b0 = __float_as_uint(Vsm[(ks * 8 + t) * LDV + nt * 8 + g]);
                uint32_t b1 = __float_as_uint(Vsm[(ks * 8 + t + 4) * LDV + nt * 8 + g]);
                mma_tf32(oacc[nt], pa, b0, b1);
            }
        }
        __syncwarp();   // P reads done before next iteration's P writes
    }

    // ---- Epilogue: normalize, store to AO [b][s][h*64+dk] ----
    float inv0 = (l0 > 0.f) ? (1.0f / l0) : 0.0f;
    float inv1 = (l1 > 0.f) ? (1.0f / l1) : 0.0f;
    int qr0 = q0 + w * 16 + g;
    size_t base0 = ((size_t)b * SS + qr0) * DD + h * DKK;
    size_t base1 = base0 + (size_t)8 * DD;
#pragma unroll
    for (int nt = 0; nt < 8; nt++) {
        *(float2*)&AO[base0 + nt * 8 + 2 * t] =
            make_float2(oacc[nt][0] * inv0, oacc[nt][1] * inv0);
        *(float2*)&AO[base1 + nt * 8 + 2 * t] =
            make_float2(oacc[nt][2] * inv1, oacc[nt][3] * inv1);
    }
}

// ---------------------------------------------------------------------------
// Launch
// ---------------------------------------------------------------------------
extern "C" void kernel_launch(void* const* d_in, const int* in_sizes, int n_in,
                              void* d_out, int out_size)
{
    const float* q    = (const float*)d_in[0];
    const float* k    = (const float*)d_in[1];
    const float* v    = (const float*)d_in[2];
    const int*   mask = (const int*)d_in[3];
    const float* Wq   = (const float*)d_in[4];
    const float* Wk   = (const float*)d_in[5];
    const float* Wv   = (const float*)d_in[6];
    const float* Wo   = (const float*)d_in[7];
    float* out = (float*)d_out;

    float *Qh, *Kh, *Vh, *AO;
    int *kidx, *kcnt;
    cudaGetSymbolAddress((void**)&Qh, g_Qh);
    cudaGetSymbolAddress((void**)&Kh, g_Kh);
    cudaGetSymbolAddress((void**)&Vh, g_Vh);
    cudaGetSymbolAddress((void**)&AO, g_AO);
    cudaGetSymbolAddress((void**)&kidx, g_kidx);
    cudaGetSymbolAddress((void**)&kcnt, g_kcnt);

    const int gsmem = 2 * G_STAGE * (int)sizeof(float);   // 73,728 B
    cudaFuncSetAttribute(gemm3_kernel<true>,
                         cudaFuncAttributeMaxDynamicSharedMemorySize, gsmem);
    cudaFuncSetAttribute(gemm3_kernel<false>,
                         cudaFuncAttributeMaxDynamicSharedMemorySize, gsmem);

    const int fsmem = (64 * LDK + 64 * LDV + 128 * LDQ) * (int)sizeof(float);
    cudaFuncSetAttribute(flash4_kernel,
                         cudaFuncAttributeMaxDynamicSharedMemorySize, fsmem);

    compact_mask_kernel<<<BB, 32>>>(mask);

    // Fused Q/K/V projections: grid.z selects input/weight/output
    dim3 gproj(MTOT / G_BM, DD / G_BN, 3);   // (64, 4, 3)
    gemm3_kernel<true><<<gproj, 256, gsmem>>>(q, Wq, Qh, k, Wk, Kh, v, Wv, Vh);

    dim3 gflash(SS / 128, HH, BB);
    flash4_kernel<<<gflash, 256, fsmem>>>(Qh, Kh, Vh,
                                          (const int*)kidx, (const int*)kcnt, AO);

    // Output projection
    dim3 gout(MTOT / G_BM, DD / G_BN, 1);
    gemm3_kernel<false><<<gout, 256, gsmem>>>(AO, Wo, out, AO, Wo, out, AO, Wo, out);
}